// round 3
// baseline (speedup 1.0000x reference)
#include <cuda_runtime.h>
#include <math.h>

// Problem constants
constexpr int kB  = 8;
constexpr int kS  = 384;
constexpr int kD  = 768;
constexpr int kE  = 768;
constexpr int kH  = 12;
constexpr int kHD = 64;
constexpr int kR  = 2 * kS - 1;   // 767 distinct relative positions actually used

// ---------------------------------------------------------------------------
// Scratch (device globals; no runtime allocation allowed)
// ---------------------------------------------------------------------------
__device__ float g_q[kB * kH * kS * kHD];       // [B,H,S,HD]
__device__ float g_k[kB * kH * kS * kHD];
__device__ float g_v[kB * kH * kS * kHD];
__device__ float g_pk[kH * kR * kHD];           // [H,R,HD]
__device__ float g_pq[kH * kR * kHD];
__device__ float g_logits[(size_t)kB * kH * kS * kS]; // [B,H,S,S]
__device__ float g_vals[kB * kS * kE];          // [B,S,E]

// ---------------------------------------------------------------------------
// Generic GEMM: C[m,n] = sum_k A[m,k] * W[n,k] + bias[n]
// out_mode 0: C[m*N+n]
// out_mode 1: qkv head layout  [B,H,S,HD] with m=b*S+s, n=h*HD+hd
// out_mode 2: pos layout       [H,R,HD]   with m=r,    n=h*HD+hd
// ---------------------------------------------------------------------------
constexpr int GBM = 64, GBN = 64, GBK = 16;

__global__ __launch_bounds__(256) void gemm_bias_kernel(
    const float* __restrict__ A, const float* __restrict__ W,
    const float* __restrict__ bias, float* __restrict__ C,
    int M, int N, int K, int out_mode)
{
    __shared__ __align__(16) float As[GBK][68];
    __shared__ __align__(16) float Ws[GBK][68];

    const int t  = threadIdx.x;
    const int bm = blockIdx.y * GBM;
    const int bn = blockIdx.x * GBN;
    const int tx = t & 15, ty = t >> 4;

    const int lrow = t >> 2;          // 0..63
    const int lc4  = (t & 3) << 2;    // 0,4,8,12

    float acc[4][4] = {};

    for (int k0 = 0; k0 < K; k0 += GBK) {
        float4 av = make_float4(0.f, 0.f, 0.f, 0.f);
        float4 wv = make_float4(0.f, 0.f, 0.f, 0.f);
        if (bm + lrow < M) av = *(const float4*)&A[(size_t)(bm + lrow) * K + k0 + lc4];
        if (bn + lrow < N) wv = *(const float4*)&W[(size_t)(bn + lrow) * K + k0 + lc4];
        __syncthreads();
        As[lc4 + 0][lrow] = av.x; As[lc4 + 1][lrow] = av.y;
        As[lc4 + 2][lrow] = av.z; As[lc4 + 3][lrow] = av.w;
        Ws[lc4 + 0][lrow] = wv.x; Ws[lc4 + 1][lrow] = wv.y;
        Ws[lc4 + 2][lrow] = wv.z; Ws[lc4 + 3][lrow] = wv.w;
        __syncthreads();
#pragma unroll
        for (int kk = 0; kk < GBK; kk++) {
            float4 a4 = *(const float4*)&As[kk][ty << 2];
            float4 b4 = *(const float4*)&Ws[kk][tx << 2];
            float a[4] = {a4.x, a4.y, a4.z, a4.w};
            float b[4] = {b4.x, b4.y, b4.z, b4.w};
#pragma unroll
            for (int ii = 0; ii < 4; ii++)
#pragma unroll
                for (int jj = 0; jj < 4; jj++)
                    acc[ii][jj] += a[ii] * b[jj];
        }
    }

#pragma unroll
    for (int ii = 0; ii < 4; ii++) {
        int m = bm + (ty << 2) + ii;
        if (m >= M) continue;
#pragma unroll
        for (int jj = 0; jj < 4; jj++) {
            int n = bn + (tx << 2) + jj;
            float val = acc[ii][jj] + bias[n];
            if (out_mode == 0) {
                C[(size_t)m * N + n] = val;
            } else if (out_mode == 1) {
                int b = m / kS, s = m % kS, h = n / kHD, hd = n % kHD;
                C[((((size_t)b * kH) + h) * kS + s) * kHD + hd] = val;
            } else {
                int h = n / kHD, hd = n % kHD;
                C[(((size_t)h * kR) + m) * kHD + hd] = val;
            }
        }
    }
}

// ---------------------------------------------------------------------------
// Logits: logits[b,h,i,j] = (q_i.k_j + q_i.pk[i-j+383] + pq[i-j+383].k_j)/sqrt(192)
//                           + segment bias, masked.
// 32x32 tile per block, banded pk/pq window of 63 rows in smem.
// ---------------------------------------------------------------------------
constexpr int LOGITS_SMEM_FLOATS = 2 * (32 * 68) + 2 * (63 * 68); // 12920
constexpr int LOGITS_SMEM_BYTES  = LOGITS_SMEM_FLOATS * 4;        // 51680

__global__ __launch_bounds__(256) void logits_kernel(
    const float* __restrict__ q, const float* __restrict__ k,
    const float* __restrict__ pk, const float* __restrict__ pq,
    const int* __restrict__ mask, const int* __restrict__ seg,
    const float* __restrict__ sep,
    const float* __restrict__ same_bias, const float* __restrict__ cross_bias,
    const float* __restrict__ sep_scale, const float* __restrict__ sep_decay,
    float* __restrict__ logits)
{
    extern __shared__ __align__(16) float sm[];
    float* qs  = sm;                    // 32*68
    float* ks  = qs + 32 * 68;          // 32*68
    float* pks = ks + 32 * 68;          // 63*68
    float* pqs = pks + 63 * 68;         // 63*68

    __shared__ int   s_segi[32], s_segj[32], s_maskj[32];
    __shared__ float s_sepi[32], s_sepj[32];

    const int bh = blockIdx.z, b = bh / kH, h = bh % kH;
    const int i0 = blockIdx.y * 32, j0 = blockIdx.x * 32;
    const int t  = threadIdx.x;
    const int tx = t & 31, ty = t >> 5;
    const int rb = i0 - j0 + 352;       // first pk/pq row of the 63-row window

    const float* qbase = q + (((size_t)b * kH + h) * kS + i0) * kHD;
    const float* kbase = k + (((size_t)b * kH + h) * kS + j0) * kHD;

    for (int l = t; l < 32 * 16; l += 256) {
        int row = l >> 4, c4 = (l & 15) << 2;
        *(float4*)&qs[row * 68 + c4] = *(const float4*)&qbase[row * kHD + c4];
        *(float4*)&ks[row * 68 + c4] = *(const float4*)&kbase[row * kHD + c4];
    }
    for (int l = t; l < 63 * 16; l += 256) {
        int row = l >> 4, c4 = (l & 15) << 2;
        size_t g = (((size_t)h * kR) + rb + row) * kHD + c4;
        *(float4*)&pks[row * 68 + c4] = *(const float4*)&pk[g];
        *(float4*)&pqs[row * 68 + c4] = *(const float4*)&pq[g];
    }
    if (t < 32) {
        s_segi[t]  = seg[b * kS + i0 + t];
        s_segj[t]  = seg[b * kS + j0 + t];
        s_sepi[t]  = fabsf(sep[b * kS + i0 + t]);
        s_sepj[t]  = fabsf(sep[b * kS + j0 + t]);
        s_maskj[t] = mask[b * kS + j0 + t];
    }
    __syncthreads();

    float c2c[4] = {}, c2p[4] = {}, p2c[4] = {};
#pragma unroll
    for (int d = 0; d < kHD; d += 4) {
        float4 kv = *(const float4*)&ks[tx * 68 + d];
#pragma unroll
        for (int w = 0; w < 4; w++) {
            int il = ty + (w << 3);
            float4 qv  = *(const float4*)&qs[il * 68 + d];
            int    rl  = il - tx + 31;   // 0..62
            float4 pkv = *(const float4*)&pks[rl * 68 + d];
            float4 pqv = *(const float4*)&pqs[rl * 68 + d];
            c2c[w] += qv.x * kv.x + qv.y * kv.y + qv.z * kv.z + qv.w * kv.w;
            c2p[w] += qv.x * pkv.x + qv.y * pkv.y + qv.z * pkv.z + qv.w * pkv.w;
            p2c[w] += pqv.x * kv.x + pqv.y * kv.y + pqv.z * kv.z + pqv.w * kv.w;
        }
    }

    const float sb_same  = same_bias[h];
    const float sb_cross = cross_bias[h];
    const float scale_h  = sep_scale[h];
    const float dx       = sep_decay[h];
    const float softp    = fmaxf(dx, 0.f) + log1pf(expf(-fabsf(dx)));
    const float decay    = softp + 1e-4f;
    const float inv      = 0.07216878364870322f;  // 1/sqrt(3*HD)

    const int   j    = j0 + tx;
    const int   segj = s_segj[tx];
    const float sepj = s_sepj[tx];
    const int   mj   = s_maskj[tx];

#pragma unroll
    for (int w = 0; w < 4; w++) {
        int il = ty + (w << 3);
        int i  = i0 + il;
        float val = (c2c[w] + c2p[w] + p2c[w]) * inv;
        if (s_segi[il] == segj) {
            val += sb_same;
        } else {
            float gap = fabsf(s_sepi[il] - sepj);
            val += sb_cross + expf(-gap * decay) * scale_h;
        }
        if (mj == 0) val = -9e15f;
        logits[(((size_t)bh * kS) + i) * kS + j] = val;
    }
}

// ---------------------------------------------------------------------------
// Row softmax over S=384, one block of 128 threads per row
// ---------------------------------------------------------------------------
__global__ __launch_bounds__(128) void softmax_kernel(float* __restrict__ logits)
{
    const size_t row = blockIdx.x;
    float* p = logits + row * kS;
    const int t = threadIdx.x;

    float v0 = p[t], v1 = p[t + 128], v2 = p[t + 256];
    float m = fmaxf(v0, fmaxf(v1, v2));

    __shared__ float red[4];
#pragma unroll
    for (int o = 16; o; o >>= 1) m = fmaxf(m, __shfl_xor_sync(0xffffffffu, m, o));
    if ((t & 31) == 0) red[t >> 5] = m;
    __syncthreads();
    m = fmaxf(fmaxf(red[0], red[1]), fmaxf(red[2], red[3]));

    float e0 = expf(v0 - m), e1 = expf(v1 - m), e2 = expf(v2 - m);
    float s = e0 + e1 + e2;
#pragma unroll
    for (int o = 16; o; o >>= 1) s += __shfl_xor_sync(0xffffffffu, s, o);
    __shared__ float red2[4];
    if ((t & 31) == 0) red2[t >> 5] = s;
    __syncthreads();
    s = red2[0] + red2[1] + red2[2] + red2[3];

    float r = 1.f / s;
    p[t] = e0 * r; p[t + 128] = e1 * r; p[t + 256] = e2 * r;
}

// ---------------------------------------------------------------------------
// AV: vals[b,i,h*HD+d] = sum_j attn[b,h,i,j] * v[b,h,j,d]
// 64 rows x 64 cols per block, K-tiles of 32
// ---------------------------------------------------------------------------
__global__ __launch_bounds__(256) void av_kernel(
    const float* __restrict__ attn, const float* __restrict__ v,
    float* __restrict__ vals)
{
    __shared__ __align__(16) float As[32][68];  // [k][m]
    __shared__ __align__(16) float Vs[32][68];  // [k][n]

    const int bh = blockIdx.y, b = bh / kH, h = bh % kH;
    const int i0 = blockIdx.x * 64;
    const float* A = attn + (size_t)bh * kS * kS;
    const float* V = v + (size_t)bh * kS * kHD;

    const int t  = threadIdx.x;
    const int tx = t & 15, ty = t >> 4;

    float acc[4][4] = {};

    for (int k0 = 0; k0 < kS; k0 += 32) {
        float4 ar[2], vr[2];
#pragma unroll
        for (int l = 0; l < 2; l++) {
            int lin = t + 256 * l;
            int arow = lin >> 3, ac4 = (lin & 7) << 2;   // 64 x 32 tile
            ar[l] = *(const float4*)&A[(size_t)(i0 + arow) * kS + k0 + ac4];
            int vrow = lin >> 4, vc4 = (lin & 15) << 2;  // 32 x 64 tile
            vr[l] = *(const float4*)&V[(size_t)(k0 + vrow) * kHD + vc4];
        }
        __syncthreads();
#pragma unroll
        for (int l = 0; l < 2; l++) {
            int lin = t + 256 * l;
            int arow = lin >> 3, ac4 = (lin & 7) << 2;
            As[ac4 + 0][arow] = ar[l].x; As[ac4 + 1][arow] = ar[l].y;
            As[ac4 + 2][arow] = ar[l].z; As[ac4 + 3][arow] = ar[l].w;
            int vrow = lin >> 4, vc4 = (lin & 15) << 2;
            *(float4*)&Vs[vrow][vc4] = vr[l];
        }
        __syncthreads();
#pragma unroll
        for (int kk = 0; kk < 32; kk++) {
            float4 a4 = *(const float4*)&As[kk][ty << 2];
            float4 b4 = *(const float4*)&Vs[kk][tx << 2];
            float a[4] = {a4.x, a4.y, a4.z, a4.w};
            float bb[4] = {b4.x, b4.y, b4.z, b4.w};
#pragma unroll
            for (int ii = 0; ii < 4; ii++)
#pragma unroll
                for (int jj = 0; jj < 4; jj++)
                    acc[ii][jj] += a[ii] * bb[jj];
        }
    }

#pragma unroll
    for (int ii = 0; ii < 4; ii++) {
        int i = i0 + (ty << 2) + ii;
#pragma unroll
        for (int jj = 0; jj < 4; jj++) {
            int d = (tx << 2) + jj;
            vals[((size_t)b * kS + i) * kE + h * kHD + d] = acc[ii][jj];
        }
    }
}

// ---------------------------------------------------------------------------
// Launch
// ---------------------------------------------------------------------------
extern "C" void kernel_launch(void* const* d_in, const int* in_sizes, int n_in,
                              void* d_out, int out_size)
{
    const float* x    = (const float*)d_in[0];
    const int*   mask = (const int*)d_in[1];
    const int*   seg  = (const int*)d_in[2];
    const float* sep  = (const float*)d_in[3];
    const float* Wq   = (const float*)d_in[4];
    const float* bq   = (const float*)d_in[5];
    const float* Wk   = (const float*)d_in[6];
    const float* bk   = (const float*)d_in[7];
    const float* Wv   = (const float*)d_in[8];
    const float* bv   = (const float*)d_in[9];
    const float* rel  = (const float*)d_in[10];
    const float* Wpk  = (const float*)d_in[11];
    const float* bpk  = (const float*)d_in[12];
    const float* Wpq  = (const float*)d_in[13];
    const float* bpq  = (const float*)d_in[14];
    const float* same_b  = (const float*)d_in[15];
    const float* cross_b = (const float*)d_in[16];
    const float* sscale  = (const float*)d_in[17];
    const float* sdecay  = (const float*)d_in[18];
    const float* Wo   = (const float*)d_in[19];
    const float* bo   = (const float*)d_in[20];
    float* out = (float*)d_out;

    float *q_, *k_, *v_, *pk_, *pq_, *lg_, *vl_;
    cudaGetSymbolAddress((void**)&q_,  g_q);
    cudaGetSymbolAddress((void**)&k_,  g_k);
    cudaGetSymbolAddress((void**)&v_,  g_v);
    cudaGetSymbolAddress((void**)&pk_, g_pk);
    cudaGetSymbolAddress((void**)&pq_, g_pq);
    cudaGetSymbolAddress((void**)&lg_, g_logits);
    cudaGetSymbolAddress((void**)&vl_, g_vals);

    cudaFuncSetAttribute(logits_kernel,
                         cudaFuncAttributeMaxDynamicSharedMemorySize,
                         LOGITS_SMEM_BYTES);

    // 1) Q, K, V projections  ([B*S,D] @ [E,D]^T) -> [B,H,S,HD]
    dim3 gproj(kE / GBN, (kB * kS) / GBM);
    gemm_bias_kernel<<<gproj, 256>>>(x, Wq, bq, q_, kB * kS, kE, kD, 1);
    gemm_bias_kernel<<<gproj, 256>>>(x, Wk, bk, k_, kB * kS, kE, kD, 1);
    gemm_bias_kernel<<<gproj, 256>>>(x, Wv, bv, v_, kB * kS, kE, kD, 1);

    // 2) Positional projections: rows 128..894 of rel_emb -> [H,R,HD]
    dim3 gpos(kE / GBN, (kR + GBM - 1) / GBM);
    const float* relbase = rel + (size_t)128 * kD;
    gemm_bias_kernel<<<gpos, 256>>>(relbase, Wpk, bpk, pk_, kR, kE, kD, 2);
    gemm_bias_kernel<<<gpos, 256>>>(relbase, Wpq, bpq, pq_, kR, kE, kD, 2);

    // 3) Logits + segment bias + mask
    dim3 glog(kS / 32, kS / 32, kB * kH);
    logits_kernel<<<glog, 256, LOGITS_SMEM_BYTES>>>(
        q_, k_, pk_, pq_, mask, seg, sep,
        same_b, cross_b, sscale, sdecay, lg_);

    // 4) Softmax over keys
    softmax_kernel<<<kB * kH * kS, 128>>>(lg_);

    // 5) attn @ V -> vals [B,S,E]
    dim3 gav(kS / 64, kB * kH);
    av_kernel<<<gav, 256>>>(lg_, v_, vl_);

    // 6) Output projection: vals @ Wo^T + bo -> [B,S,D]
    dim3 gout(kD / GBN, (kB * kS) / GBM);
    gemm_bias_kernel<<<gout, 256>>>(vl_, Wo, bo, out, kB * kS, kD, kE, 0);
}

// round 5
// speedup vs baseline: 1.5750x; 1.5750x over previous
#include <cuda_runtime.h>
#include <cuda_bf16.h>
#include <math.h>
#include <stdint.h>

// Problem constants
constexpr int kB  = 8;
constexpr int kS  = 384;
constexpr int kD  = 768;
constexpr int kE  = 768;
constexpr int kH  = 12;
constexpr int kHD = 64;
constexpr int kR  = 2 * kS - 1;   // 767 distinct relative positions actually used
constexpr int kK3 = 3 * kD;       // 2304: bf16-split concatenated K

// ---------------------------------------------------------------------------
// Scratch (device globals; no runtime allocation allowed)
// ---------------------------------------------------------------------------
__device__ float g_q[kB * kH * kS * kHD];       // [B,H,S,HD]
__device__ float g_k[kB * kH * kS * kHD];
__device__ float g_v[kB * kH * kS * kHD];
__device__ float g_pk[kH * kR * kHD];           // [H,R,HD]
__device__ float g_pq[kH * kR * kHD];
__device__ float g_logits[(size_t)kB * kH * kS * kS]; // [B,H,S,S]
__device__ float g_vals[kB * kS * kE];          // [B,S,E]

// bf16-split operand buffers
__device__ unsigned short g_ab[3072 * kK3];      // A-split for x / vals (reused)
__device__ unsigned short g_wqkv[2304 * kK3];    // [Wq|Wk|Wv] split
__device__ unsigned short g_apos[768 * kK3];     // rel rows split (padded to 768)
__device__ unsigned short g_wpos[1536 * kK3];    // [Wpk|Wpq] split; reused for Wo

// ---------------------------------------------------------------------------
// PTX helpers (target-independent: cp.async, ldmatrix, mma.sync — sm_80+)
// ---------------------------------------------------------------------------
__device__ __forceinline__ uint32_t smem_to_u32(const void* p) {
    uint32_t a;
    asm("{ .reg .u64 t; cvta.to.shared.u64 t, %1; cvt.u32.u64 %0, t; }"
        : "=r"(a) : "l"(p));
    return a;
}

__device__ __forceinline__ void cp_async16(uint32_t saddr, const void* gptr) {
    asm volatile("cp.async.cg.shared.global [%0], [%1], 16;\n"
                 :: "r"(saddr), "l"(gptr));
}
#define CP_COMMIT()  asm volatile("cp.async.commit_group;\n" ::: "memory")
#define CP_WAIT(n)   asm volatile("cp.async.wait_group %0;\n" :: "n"(n) : "memory")

__device__ __forceinline__ void ldmatrix_x4(uint32_t* r, uint32_t addr) {
    asm volatile("ldmatrix.sync.aligned.m8n8.x4.shared.b16 {%0,%1,%2,%3}, [%4];"
                 : "=r"(r[0]), "=r"(r[1]), "=r"(r[2]), "=r"(r[3]) : "r"(addr));
}
__device__ __forceinline__ void ldmatrix_x2(uint32_t* r, uint32_t addr) {
    asm volatile("ldmatrix.sync.aligned.m8n8.x2.shared.b16 {%0,%1}, [%2];"
                 : "=r"(r[0]), "=r"(r[1]) : "r"(addr));
}

__device__ __forceinline__ void mma_bf16(float* d, const uint32_t* a, const uint32_t* b) {
    asm volatile(
        "mma.sync.aligned.m16n8k16.row.col.f32.bf16.bf16.f32 "
        "{%0,%1,%2,%3}, {%4,%5,%6,%7}, {%8,%9}, {%0,%1,%2,%3};"
        : "+f"(d[0]), "+f"(d[1]), "+f"(d[2]), "+f"(d[3])
        : "r"(a[0]), "r"(a[1]), "r"(a[2]), "r"(a[3]),
          "r"(b[0]), "r"(b[1]));
}

// ---------------------------------------------------------------------------
// fp32 -> bf16 hi/lo split conversion kernels
// A pattern:  out[m, 0:K]=hi, [K:2K]=hi, [2K:3K]=lo
// W pattern:  out[n, 0:K]=hi, [K:2K]=lo, [2K:3K]=hi
// => sum over K'=3K of A^.W^ = A_hi.W_hi + A_hi.W_lo + A_lo.W_hi  (~fp32)
// ---------------------------------------------------------------------------
union BF4 { __nv_bfloat16 h[4]; uint2 u; };

__device__ __forceinline__ void split4(float4 a, uint2& hi, uint2& lo)
{
    float v[4] = {a.x, a.y, a.z, a.w};
    BF4 H, L;
#pragma unroll
    for (int i = 0; i < 4; i++) {
        __nv_bfloat16 h1 = __float2bfloat16_rn(v[i]);
        float res = v[i] - __bfloat162float(h1);
        H.h[i] = h1;
        L.h[i] = __float2bfloat16_rn(res);
    }
    hi = H.u; lo = L.u;
}

__global__ __launch_bounds__(256) void split_a_kernel(
    const float* __restrict__ A, unsigned short* __restrict__ out,
    int Msrc, int Mpad, int K)
{
    int idx = blockIdx.x * 256 + threadIdx.x;
    int kq = K >> 2;
    if (idx >= Mpad * kq) return;
    int m = idx / kq;
    int c4 = (idx - m * kq) << 2;
    float4 a = (m < Msrc) ? *(const float4*)(A + (size_t)m * K + c4)
                          : make_float4(0.f, 0.f, 0.f, 0.f);
    uint2 hi, lo; split4(a, hi, lo);
    size_t base = (size_t)m * 3 * K + c4;
    *(uint2*)(out + base)         = hi;
    *(uint2*)(out + base + K)     = hi;
    *(uint2*)(out + base + 2 * K) = lo;
}

__global__ __launch_bounds__(256) void split_w_kernel(
    const float* __restrict__ W0, const float* __restrict__ W1,
    const float* __restrict__ W2, unsigned short* __restrict__ out,
    int nsrc, int K)
{
    int idx = blockIdx.x * 256 + threadIdx.x;
    int kq = K >> 2;
    int rows = nsrc * 768;
    if (idx >= rows * kq) return;
    int rr = idx / kq;
    int c4 = (idx - rr * kq) << 2;
    int s = rr / 768, r = rr - s * 768;
    const float* W = (s == 0) ? W0 : (s == 1) ? W1 : W2;
    float4 a = *(const float4*)(W + (size_t)r * K + c4);
    uint2 hi, lo; split4(a, hi, lo);
    size_t base = (size_t)rr * 3 * K + c4;
    *(uint2*)(out + base)         = hi;
    *(uint2*)(out + base + K)     = lo;
    *(uint2*)(out + base + 2 * K) = hi;
}

// ---------------------------------------------------------------------------
// bf16 HMMA GEMM:  C[m,n] = sum_{k<K3} A[m,k]*B[n,k]  (+bias, mapped out)
// 128x128 CTA tile, BK=64, 256 threads = 8 warps (2 M x 4 N), warp tile 64x32.
// cp.async double-buffered smem, ldmatrix + mma.sync m16n8k16 bf16->f32.
// mode 0: QKV   n -> {q,k,v}[b,h,s,hd]
// mode 1: POS   n -> {pk,pq}[h,r,hd]
// mode 2: plain C[m*768+n]
// ---------------------------------------------------------------------------
constexpr int BK   = 64;
constexpr int LDT  = 72;                       // smem stride in halves (pad 8)
constexpr int TBUF = 128 * LDT * 2;            // 18432 bytes per tile buffer
constexpr int TGEMM_SMEM = 4 * TBUF;           // A0,B0,A1,B1 = 73728

__device__ __forceinline__ void store_pair(
    int mode, int Msrc, int mrow, int n, float v0, float v1,
    const float* __restrict__ b0, const float* __restrict__ b1,
    const float* __restrict__ b2,
    float* __restrict__ o0, float* __restrict__ o1, float* __restrict__ o2)
{
    if (mrow >= Msrc) return;
    if (mode == 2) {
        float2 w = make_float2(v0 + b0[n], v1 + b0[n + 1]);
        *(float2*)&o0[(size_t)mrow * 768 + n] = w;
    } else {
        int which = n / 768;
        int e = n - which * 768;
        int h = e >> 6, hd = e & 63;
        const float* bp = (which == 0) ? b0 : (which == 1) ? b1 : b2;
        float*       op = (which == 0) ? o0 : (which == 1) ? o1 : o2;
        float2 w = make_float2(v0 + bp[e], v1 + bp[e + 1]);
        size_t off;
        if (mode == 0) {
            int bi = mrow / kS, s = mrow - bi * kS;
            off = ((((size_t)bi * kH) + h) * kS + s) * (size_t)kHD + hd;
        } else {
            off = (((size_t)h * kR) + mrow) * (size_t)kHD + hd;
        }
        *(float2*)&op[off] = w;
    }
}

__global__ __launch_bounds__(256) void tgemm_kernel(
    const __nv_bfloat16* __restrict__ A, const __nv_bfloat16* __restrict__ B,
    int K3, int Msrc,
    const float* __restrict__ bias0, const float* __restrict__ bias1,
    const float* __restrict__ bias2,
    float* __restrict__ out0, float* __restrict__ out1, float* __restrict__ out2,
    int mode)
{
    extern __shared__ __align__(16) char smem[];
    const uint32_t sbase = smem_to_u32(smem);

    const int t = threadIdx.x, lane = t & 31, wid = t >> 5;
    const int warp_m = wid & 1, warp_n = wid >> 1;   // 2 x 4
    const int m0 = blockIdx.y * 128, n0 = blockIdx.x * 128;

    const __nv_bfloat16* Ag = A + (size_t)m0 * K3;
    const __nv_bfloat16* Bg = B + (size_t)n0 * K3;
    const int NC = K3 / BK;

    // per-thread load slots: idx = it*256 + t, row = idx>>3, c8 = idx&7
    const int lrow = t >> 3;          // base row step of 32 per 'it'
    const int lc8  = (t & 7) * 8;     // half-offset within row

    auto issue = [&](int c) {
        const int buf = c & 1;
        const uint32_t dA = sbase + buf * 2 * TBUF;
        const uint32_t dB = dA + TBUF;
        const __nv_bfloat16* Ak = Ag + (size_t)c * BK;
        const __nv_bfloat16* Bk = Bg + (size_t)c * BK;
#pragma unroll
        for (int it = 0; it < 4; it++) {
            int r = lrow + it * 32;
            uint32_t so = (uint32_t)(r * LDT + lc8) * 2;
            cp_async16(dA + so, Ak + (size_t)r * K3 + lc8);
            cp_async16(dB + so, Bk + (size_t)r * K3 + lc8);
        }
        CP_COMMIT();
    };

    float d[4][4][4];
#pragma unroll
    for (int i = 0; i < 4; i++)
#pragma unroll
        for (int j = 0; j < 4; j++)
#pragma unroll
            for (int e = 0; e < 4; e++) d[i][j][e] = 0.f;

    // ldmatrix lane address components (in halves)
    const int a_row = warp_m * 64 + (lane & 15);       // + i*16
    const int a_col = (lane >> 4) * 8;                 // + ks
    const int b_row = warp_n * 32 + (lane & 7);        // + j*8
    const int b_col = ((lane >> 3) & 1) * 8;           // + ks

    issue(0);

    for (int c = 0; c < NC; c++) {
        if (c + 1 < NC) { issue(c + 1); CP_WAIT(1); }
        else           { CP_WAIT(0); }
        __syncthreads();

        const int buf = c & 1;
        const uint32_t sA = sbase + buf * 2 * TBUF;
        const uint32_t sB = sA + TBUF;

#pragma unroll
        for (int ks = 0; ks < BK; ks += 16) {
            uint32_t a[4][4], b[4][2];
#pragma unroll
            for (int i = 0; i < 4; i++)
                ldmatrix_x4(a[i], sA + (uint32_t)((a_row + i * 16) * LDT + a_col + ks) * 2);
#pragma unroll
            for (int j = 0; j < 4; j++)
                ldmatrix_x2(b[j], sB + (uint32_t)((b_row + j * 8) * LDT + b_col + ks) * 2);
#pragma unroll
            for (int i = 0; i < 4; i++)
#pragma unroll
                for (int j = 0; j < 4; j++)
                    mma_bf16(d[i][j], a[i], b[j]);
        }
        __syncthreads();
    }

    // Epilogue: lane (row = lane/4 [+8], cols = (lane%4)*2, +1)
    const int mbase = m0 + warp_m * 64 + (lane >> 2);
    const int nbase = n0 + warp_n * 32 + (lane & 3) * 2;
#pragma unroll
    for (int i = 0; i < 4; i++) {
#pragma unroll
        for (int j = 0; j < 4; j++) {
            int mm = mbase + i * 16;
            int nn = nbase + j * 8;
            store_pair(mode, Msrc, mm,     nn, d[i][j][0], d[i][j][1],
                       bias0, bias1, bias2, out0, out1, out2);
            store_pair(mode, Msrc, mm + 8, nn, d[i][j][2], d[i][j][3],
                       bias0, bias1, bias2, out0, out1, out2);
        }
    }
}

// ---------------------------------------------------------------------------
// Logits: logits[b,h,i,j] = (q_i.k_j + q_i.pk[i-j+383] + pq[i-j+383].k_j)/sqrt(192)
//                           + segment bias, masked.  (unchanged, FFMA)
// ---------------------------------------------------------------------------
constexpr int LOGITS_SMEM_FLOATS = 2 * (32 * 68) + 2 * (63 * 68);
constexpr int LOGITS_SMEM_BYTES  = LOGITS_SMEM_FLOATS * 4;

__global__ __launch_bounds__(256) void logits_kernel(
    const float* __restrict__ q, const float* __restrict__ k,
    const float* __restrict__ pk, const float* __restrict__ pq,
    const int* __restrict__ mask, const int* __restrict__ seg,
    const float* __restrict__ sep,
    const float* __restrict__ same_bias, const float* __restrict__ cross_bias,
    const float* __restrict__ sep_scale, const float* __restrict__ sep_decay,
    float* __restrict__ logits)
{
    extern __shared__ __align__(16) float sm[];
    float* qs  = sm;
    float* ks  = qs + 32 * 68;
    float* pks = ks + 32 * 68;
    float* pqs = pks + 63 * 68;

    __shared__ int   s_segi[32], s_segj[32], s_maskj[32];
    __shared__ float s_sepi[32], s_sepj[32];

    const int bh = blockIdx.z, b = bh / kH, h = bh % kH;
    const int i0 = blockIdx.y * 32, j0 = blockIdx.x * 32;
    const int t  = threadIdx.x;
    const int tx = t & 31, ty = t >> 5;
    const int rb = i0 - j0 + 352;

    const float* qbase = q + (((size_t)b * kH + h) * kS + i0) * kHD;
    const float* kbase = k + (((size_t)b * kH + h) * kS + j0) * kHD;

    for (int l = t; l < 32 * 16; l += 256) {
        int row = l >> 4, c4 = (l & 15) << 2;
        *(float4*)&qs[row * 68 + c4] = *(const float4*)&qbase[row * kHD + c4];
        *(float4*)&ks[row * 68 + c4] = *(const float4*)&kbase[row * kHD + c4];
    }
    for (int l = t; l < 63 * 16; l += 256) {
        int row = l >> 4, c4 = (l & 15) << 2;
        size_t g = (((size_t)h * kR) + rb + row) * kHD + c4;
        *(float4*)&pks[row * 68 + c4] = *(const float4*)&pk[g];
        *(float4*)&pqs[row * 68 + c4] = *(const float4*)&pq[g];
    }
    if (t < 32) {
        s_segi[t]  = seg[b * kS + i0 + t];
        s_segj[t]  = seg[b * kS + j0 + t];
        s_sepi[t]  = fabsf(sep[b * kS + i0 + t]);
        s_sepj[t]  = fabsf(sep[b * kS + j0 + t]);
        s_maskj[t] = mask[b * kS + j0 + t];
    }
    __syncthreads();

    float c2c[4] = {}, c2p[4] = {}, p2c[4] = {};
#pragma unroll
    for (int dd = 0; dd < kHD; dd += 4) {
        float4 kv = *(const float4*)&ks[tx * 68 + dd];
#pragma unroll
        for (int w = 0; w < 4; w++) {
            int il = ty + (w << 3);
            float4 qv  = *(const float4*)&qs[il * 68 + dd];
            int    rl  = il - tx + 31;
            float4 pkv = *(const float4*)&pks[rl * 68 + dd];
            float4 pqv = *(const float4*)&pqs[rl * 68 + dd];
            c2c[w] += qv.x * kv.x + qv.y * kv.y + qv.z * kv.z + qv.w * kv.w;
            c2p[w] += qv.x * pkv.x + qv.y * pkv.y + qv.z * pkv.z + qv.w * pkv.w;
            p2c[w] += pqv.x * kv.x + pqv.y * kv.y + pqv.z * kv.z + pqv.w * kv.w;
        }
    }

    const float sb_same  = same_bias[h];
    const float sb_cross = cross_bias[h];
    const float scale_h  = sep_scale[h];
    const float dx       = sep_decay[h];
    const float softp    = fmaxf(dx, 0.f) + log1pf(expf(-fabsf(dx)));
    const float decay    = softp + 1e-4f;
    const float inv      = 0.07216878364870322f;

    const int   j    = j0 + tx;
    const int   segj = s_segj[tx];
    const float sepj = s_sepj[tx];
    const int   mj   = s_maskj[tx];

#pragma unroll
    for (int w = 0; w < 4; w++) {
        int il = ty + (w << 3);
        int i  = i0 + il;
        float val = (c2c[w] + c2p[w] + p2c[w]) * inv;
        if (s_segi[il] == segj) {
            val += sb_same;
        } else {
            float gap = fabsf(s_sepi[il] - sepj);
            val += sb_cross + expf(-gap * decay) * scale_h;
        }
        if (mj == 0) val = -9e15f;
        logits[(((size_t)bh * kS) + i) * kS + j] = val;
    }
}

// ---------------------------------------------------------------------------
// Row softmax over S=384  (unchanged)
// ---------------------------------------------------------------------------
__global__ __launch_bounds__(128) void softmax_kernel(float* __restrict__ logits)
{
    const size_t row = blockIdx.x;
    float* p = logits + row * kS;
    const int t = threadIdx.x;

    float v0 = p[t], v1 = p[t + 128], v2 = p[t + 256];
    float m = fmaxf(v0, fmaxf(v1, v2));

    __shared__ float red[4];
#pragma unroll
    for (int o = 16; o; o >>= 1) m = fmaxf(m, __shfl_xor_sync(0xffffffffu, m, o));
    if ((t & 31) == 0) red[t >> 5] = m;
    __syncthreads();
    m = fmaxf(fmaxf(red[0], red[1]), fmaxf(red[2], red[3]));

    float e0 = expf(v0 - m), e1 = expf(v1 - m), e2 = expf(v2 - m);
    float s = e0 + e1 + e2;
#pragma unroll
    for (int o = 16; o; o >>= 1) s += __shfl_xor_sync(0xffffffffu, s, o);
    __shared__ float red2[4];
    if ((t & 31) == 0) red2[t >> 5] = s;
    __syncthreads();
    s = red2[0] + red2[1] + red2[2] + red2[3];

    float r = 1.f / s;
    p[t] = e0 * r; p[t + 128] = e1 * r; p[t + 256] = e2 * r;
}

// ---------------------------------------------------------------------------
// AV: vals[b,i,h*HD+d] = sum_j attn[b,h,i,j] * v[b,h,j,d]  (unchanged)
// ---------------------------------------------------------------------------
__global__ __launch_bounds__(256) void av_kernel(
    const float* __restrict__ attn, const float* __restrict__ v,
    float* __restrict__ vals)
{
    __shared__ __align__(16) float As[32][68];
    __shared__ __align__(16) float Vs[32][68];

    const int bh = blockIdx.y, b = bh / kH, h = bh % kH;
    const int i0 = blockIdx.x * 64;
    const float* A = attn + (size_t)bh * kS * kS;
    const float* V = v + (size_t)bh * kS * kHD;

    const int t  = threadIdx.x;
    const int tx = t & 15, ty = t >> 4;

    float acc[4][4] = {};

    for (int k0 = 0; k0 < kS; k0 += 32) {
        float4 ar[2], vr[2];
#pragma unroll
        for (int l = 0; l < 2; l++) {
            int lin = t + 256 * l;
            int arow = lin >> 3, ac4 = (lin & 7) << 2;
            ar[l] = *(const float4*)&A[(size_t)(i0 + arow) * kS + k0 + ac4];
            int vrow = lin >> 4, vc4 = (lin & 15) << 2;
            vr[l] = *(const float4*)&V[(size_t)(k0 + vrow) * kHD + vc4];
        }
        __syncthreads();
#pragma unroll
        for (int l = 0; l < 2; l++) {
            int lin = t + 256 * l;
            int arow = lin >> 3, ac4 = (lin & 7) << 2;
            As[ac4 + 0][arow] = ar[l].x; As[ac4 + 1][arow] = ar[l].y;
            As[ac4 + 2][arow] = ar[l].z; As[ac4 + 3][arow] = ar[l].w;
            int vrow = lin >> 4, vc4 = (lin & 15) << 2;
            *(float4*)&Vs[vrow][vc4] = vr[l];
        }
        __syncthreads();
#pragma unroll
        for (int kk = 0; kk < 32; kk++) {
            float4 a4 = *(const float4*)&As[kk][ty << 2];
            float4 b4 = *(const float4*)&Vs[kk][tx << 2];
            float a[4] = {a4.x, a4.y, a4.z, a4.w};
            float bb[4] = {b4.x, b4.y, b4.z, b4.w};
#pragma unroll
            for (int ii = 0; ii < 4; ii++)
#pragma unroll
                for (int jj = 0; jj < 4; jj++)
                    acc[ii][jj] += a[ii] * bb[jj];
        }
    }

#pragma unroll
    for (int ii = 0; ii < 4; ii++) {
        int i = i0 + (ty << 2) + ii;
#pragma unroll
        for (int jj = 0; jj < 4; jj++) {
            int dd = (tx << 2) + jj;
            vals[((size_t)b * kS + i) * kE + h * kHD + dd] = acc[ii][jj];
        }
    }
}

// ---------------------------------------------------------------------------
// Launch
// ---------------------------------------------------------------------------
extern "C" void kernel_launch(void* const* d_in, const int* in_sizes, int n_in,
                              void* d_out, int out_size)
{
    const float* x    = (const float*)d_in[0];
    const int*   mask = (const int*)d_in[1];
    const int*   seg  = (const int*)d_in[2];
    const float* sep  = (const float*)d_in[3];
    const float* Wq   = (const float*)d_in[4];
    const float* bq   = (const float*)d_in[5];
    const float* Wk   = (const float*)d_in[6];
    const float* bk   = (const float*)d_in[7];
    const float* Wv   = (const float*)d_in[8];
    const float* bv   = (const float*)d_in[9];
    const float* rel  = (const float*)d_in[10];
    const float* Wpk  = (const float*)d_in[11];
    const float* bpk  = (const float*)d_in[12];
    const float* Wpq  = (const float*)d_in[13];
    const float* bpq  = (const float*)d_in[14];
    const float* same_b  = (const float*)d_in[15];
    const float* cross_b = (const float*)d_in[16];
    const float* sscale  = (const float*)d_in[17];
    const float* sdecay  = (const float*)d_in[18];
    const float* Wo   = (const float*)d_in[19];
    const float* bo   = (const float*)d_in[20];
    float* out = (float*)d_out;

    float *q_, *k_, *v_, *pk_, *pq_, *lg_, *vl_;
    unsigned short *ab_, *wqkv_, *apos_, *wpos_;
    cudaGetSymbolAddress((void**)&q_,  g_q);
    cudaGetSymbolAddress((void**)&k_,  g_k);
    cudaGetSymbolAddress((void**)&v_,  g_v);
    cudaGetSymbolAddress((void**)&pk_, g_pk);
    cudaGetSymbolAddress((void**)&pq_, g_pq);
    cudaGetSymbolAddress((void**)&lg_, g_logits);
    cudaGetSymbolAddress((void**)&vl_, g_vals);
    cudaGetSymbolAddress((void**)&ab_,   g_ab);
    cudaGetSymbolAddress((void**)&wqkv_, g_wqkv);
    cudaGetSymbolAddress((void**)&apos_, g_apos);
    cudaGetSymbolAddress((void**)&wpos_, g_wpos);

    cudaFuncSetAttribute(logits_kernel,
                         cudaFuncAttributeMaxDynamicSharedMemorySize,
                         LOGITS_SMEM_BYTES);
    cudaFuncSetAttribute(tgemm_kernel,
                         cudaFuncAttributeMaxDynamicSharedMemorySize,
                         TGEMM_SMEM);

    const int kq = kD / 4;  // 192

    // 1) operand splits (fp32 -> bf16 hi/lo, K-concat)
    split_a_kernel<<<(3072 * kq + 255) / 256, 256>>>(x, ab_, 3072, 3072, kD);
    split_w_kernel<<<(2304 * kq + 255) / 256, 256>>>(Wq, Wk, Wv, wqkv_, 3, kD);
    split_a_kernel<<<(768 * kq + 255) / 256, 256>>>(rel + (size_t)128 * kD, apos_, kR, 768, kD);
    split_w_kernel<<<(1536 * kq + 255) / 256, 256>>>(Wpk, Wpq, Wpq, wpos_, 2, kD);

    // 2) QKV projection (merged): M=3072, N=2304, K'=2304
    tgemm_kernel<<<dim3(18, 24), 256, TGEMM_SMEM>>>(
        (const __nv_bfloat16*)ab_, (const __nv_bfloat16*)wqkv_, kK3, 3072,
        bq, bk, bv, q_, k_, v_, 0);

    // 3) positional projections (merged): M=767(pad 768), N=1536
    tgemm_kernel<<<dim3(12, 6), 256, TGEMM_SMEM>>>(
        (const __nv_bfloat16*)apos_, (const __nv_bfloat16*)wpos_, kK3, kR,
        bpk, bpq, nullptr, pk_, pq_, nullptr, 1);

    // 4) Logits + segment bias + mask
    dim3 glog(kS / 32, kS / 32, kB * kH);
    logits_kernel<<<glog, 256, LOGITS_SMEM_BYTES>>>(
        q_, k_, pk_, pq_, mask, seg, sep,
        same_b, cross_b, sscale, sdecay, lg_);

    // 5) Softmax over keys
    softmax_kernel<<<kB * kH * kS, 128>>>(lg_);

    // 6) attn @ V -> vals [B,S,E]
    dim3 gav(kS / 64, kB * kH);
    av_kernel<<<gav, 256>>>(lg_, v_, vl_);

    // 7) Output projection: M=3072, N=768 (reuse ab_/wpos_ buffers)
    split_a_kernel<<<(3072 * kq + 255) / 256, 256>>>(vl_, ab_, 3072, 3072, kE);
    split_w_kernel<<<(768 * kq + 255) / 256, 256>>>(Wo, Wo, Wo, wpos_, 1, kE);
    tgemm_kernel<<<dim3(6, 24), 256, TGEMM_SMEM>>>(
        (const __nv_bfloat16*)ab_, (const __nv_bfloat16*)wpos_, kK3, 3072,
        bo, nullptr, nullptr, out, nullptr, nullptr, 2);
}

// round 6
// speedup vs baseline: 2.0199x; 1.2825x over previous
#include <cuda_runtime.h>
#include <cuda_bf16.h>
#include <math.h>
#include <stdint.h>

// Problem constants
constexpr int kB  = 8;
constexpr int kS  = 384;
constexpr int kD  = 768;
constexpr int kE  = 768;
constexpr int kH  = 12;
constexpr int kHD = 64;
constexpr int kR  = 2 * kS - 1;   // 767 distinct relative positions actually used
constexpr int kK3 = 3 * kD;       // 2304: bf16-split concatenated K
constexpr int kKS = 192;          // 3*64: split head-dim for logits MMA

// ---------------------------------------------------------------------------
// Scratch (device globals; no runtime allocation allowed)
// ---------------------------------------------------------------------------
__device__ float g_v[kB * kH * kS * kHD];               // [B,H,S,HD] fp32
__device__ float g_logits[(size_t)kB * kH * kS * kS];   // [B,H,S,S]
__device__ float g_vals[kB * kS * kE];                  // [B,S,E]

// bf16-split operand buffers for projections
__device__ unsigned short g_ab[3072 * kK3];      // A-split for x / vals (reused)
__device__ unsigned short g_wqkv[2304 * kK3];    // [Wq|Wk|Wv] split
__device__ unsigned short g_apos[768 * kK3];     // rel rows split (padded to 768)
__device__ unsigned short g_wpos[1536 * kK3];    // [Wpk|Wpq] split; reused for Wo

// bf16-split logits operands (written by tgemm epilogues)
__device__ unsigned short g_qs[96 * kS * kKS];   // [bh][s][192] pattern A (hi,hi,lo)
__device__ unsigned short g_ks[96 * kS * kKS];   // [bh][s][192] pattern B (hi,lo,hi)
__device__ unsigned short g_pks[kH * 768 * kKS]; // [h][r][192]  pattern B
__device__ unsigned short g_pqs[kH * 768 * kKS]; // [h][r][192]  pattern A

// ---------------------------------------------------------------------------
// PTX helpers (target-independent: cp.async, ldmatrix, mma.sync — sm_80+)
// ---------------------------------------------------------------------------
__device__ __forceinline__ uint32_t smem_to_u32(const void* p) {
    uint32_t a;
    asm("{ .reg .u64 t; cvta.to.shared.u64 t, %1; cvt.u32.u64 %0, t; }"
        : "=r"(a) : "l"(p));
    return a;
}

__device__ __forceinline__ void cp_async16(uint32_t saddr, const void* gptr) {
    asm volatile("cp.async.cg.shared.global [%0], [%1], 16;\n"
                 :: "r"(saddr), "l"(gptr));
}
#define CP_COMMIT()  asm volatile("cp.async.commit_group;\n" ::: "memory")
#define CP_WAIT(n)   asm volatile("cp.async.wait_group %0;\n" :: "n"(n) : "memory")

__device__ __forceinline__ void ldmatrix_x4(uint32_t* r, uint32_t addr) {
    asm volatile("ldmatrix.sync.aligned.m8n8.x4.shared.b16 {%0,%1,%2,%3}, [%4];"
                 : "=r"(r[0]), "=r"(r[1]), "=r"(r[2]), "=r"(r[3]) : "r"(addr));
}
__device__ __forceinline__ void ldmatrix_x2(uint32_t* r, uint32_t addr) {
    asm volatile("ldmatrix.sync.aligned.m8n8.x2.shared.b16 {%0,%1}, [%2];"
                 : "=r"(r[0]), "=r"(r[1]) : "r"(addr));
}

__device__ __forceinline__ void mma_bf16(float* d, const uint32_t* a, const uint32_t* b) {
    asm volatile(
        "mma.sync.aligned.m16n8k16.row.col.f32.bf16.bf16.f32 "
        "{%0,%1,%2,%3}, {%4,%5,%6,%7}, {%8,%9}, {%0,%1,%2,%3};"
        : "+f"(d[0]), "+f"(d[1]), "+f"(d[2]), "+f"(d[3])
        : "r"(a[0]), "r"(a[1]), "r"(a[2]), "r"(a[3]),
          "r"(b[0]), "r"(b[1]));
}

// ---------------------------------------------------------------------------
// fp32 -> bf16 hi/lo split conversion kernels (operands for projections)
// A pattern:  out[m, 0:K]=hi, [K:2K]=hi, [2K:3K]=lo
// W pattern:  out[n, 0:K]=hi, [K:2K]=lo, [2K:3K]=hi
// ---------------------------------------------------------------------------
union BF4 { __nv_bfloat16 h[4]; uint2 u; };

__device__ __forceinline__ void split4(float4 a, uint2& hi, uint2& lo)
{
    float v[4] = {a.x, a.y, a.z, a.w};
    BF4 H, L;
#pragma unroll
    for (int i = 0; i < 4; i++) {
        __nv_bfloat16 h1 = __float2bfloat16_rn(v[i]);
        float res = v[i] - __bfloat162float(h1);
        H.h[i] = h1;
        L.h[i] = __float2bfloat16_rn(res);
    }
    hi = H.u; lo = L.u;
}

__global__ __launch_bounds__(256) void split_a_kernel(
    const float* __restrict__ A, unsigned short* __restrict__ out,
    int Msrc, int Mpad, int K)
{
    int idx = blockIdx.x * 256 + threadIdx.x;
    int kq = K >> 2;
    if (idx >= Mpad * kq) return;
    int m = idx / kq;
    int c4 = (idx - m * kq) << 2;
    float4 a = (m < Msrc) ? *(const float4*)(A + (size_t)m * K + c4)
                          : make_float4(0.f, 0.f, 0.f, 0.f);
    uint2 hi, lo; split4(a, hi, lo);
    size_t base = (size_t)m * 3 * K + c4;
    *(uint2*)(out + base)         = hi;
    *(uint2*)(out + base + K)     = hi;
    *(uint2*)(out + base + 2 * K) = lo;
}

__global__ __launch_bounds__(256) void split_w_kernel(
    const float* __restrict__ W0, const float* __restrict__ W1,
    const float* __restrict__ W2, unsigned short* __restrict__ out,
    int nsrc, int K)
{
    int idx = blockIdx.x * 256 + threadIdx.x;
    int kq = K >> 2;
    int rows = nsrc * 768;
    if (idx >= rows * kq) return;
    int rr = idx / kq;
    int c4 = (idx - rr * kq) << 2;
    int s = rr / 768, r = rr - s * 768;
    const float* W = (s == 0) ? W0 : (s == 1) ? W1 : W2;
    float4 a = *(const float4*)(W + (size_t)r * K + c4);
    uint2 hi, lo; split4(a, hi, lo);
    size_t base = (size_t)rr * 3 * K + c4;
    *(uint2*)(out + base)         = hi;
    *(uint2*)(out + base + K)     = lo;
    *(uint2*)(out + base + 2 * K) = hi;
}

// ---------------------------------------------------------------------------
// bf16 HMMA GEMM (projections). 128x128 CTA tile, BK=64, 256 threads.
// mode 0: QKV   n<768 -> q split(A-pat), n<1536 -> k split(B-pat), else v fp32
// mode 1: POS   n<768 -> pk split(B-pat), else pq split(A-pat)
// mode 2: plain fp32 C[m*768+n]
// ---------------------------------------------------------------------------
constexpr int BK   = 64;
constexpr int LDT  = 72;                       // smem stride in halves (pad 8)
constexpr int TBUF = 128 * LDT * 2;            // bytes per tile buffer
constexpr int TGEMM_SMEM = 4 * TBUF;           // A0,B0,A1,B1 = 73728

__device__ __forceinline__ void store_split_pair(
    unsigned short* base, float v0, float v1, bool patA)
{
    __nv_bfloat16 h0 = __float2bfloat16_rn(v0), h1 = __float2bfloat16_rn(v1);
    float r0 = v0 - __bfloat162float(h0), r1 = v1 - __bfloat162float(h1);
    __nv_bfloat16 l0 = __float2bfloat16_rn(r0), l1 = __float2bfloat16_rn(r1);
    uint32_t hp = (uint32_t)*(unsigned short*)&h0 | ((uint32_t)*(unsigned short*)&h1 << 16);
    uint32_t lp = (uint32_t)*(unsigned short*)&l0 | ((uint32_t)*(unsigned short*)&l1 << 16);
    *(uint32_t*)(base)       = hp;
    *(uint32_t*)(base + 64)  = patA ? hp : lp;
    *(uint32_t*)(base + 128) = patA ? lp : hp;
}

__device__ __forceinline__ void store_pair(
    int mode, int Msrc, int mrow, int n, float v0, float v1,
    const float* __restrict__ b0, const float* __restrict__ b1,
    const float* __restrict__ b2,
    float* __restrict__ o0,
    unsigned short* __restrict__ s0, unsigned short* __restrict__ s1)
{
    if (mrow >= Msrc) return;
    if (mode == 2) {
        float2 w = make_float2(v0 + b0[n], v1 + b0[n + 1]);
        *(float2*)&o0[(size_t)mrow * 768 + n] = w;
        return;
    }
    int which = n / 768;
    int e = n - which * 768;
    int h = e >> 6, hd = e & 63;
    const float* bp = (which == 0) ? b0 : (which == 1) ? b1 : b2;
    float w0 = v0 + bp[e], w1 = v1 + bp[e + 1];
    if (mode == 0) {
        int bi = mrow / kS, s = mrow - bi * kS;
        if (which == 2) {
            *(float2*)&o0[((((size_t)bi * kH) + h) * kS + s) * (size_t)kHD + hd]
                = make_float2(w0, w1);
        } else {
            unsigned short* base = ((which == 0) ? s0 : s1)
                + (((size_t)(bi * kH + h) * kS) + s) * kKS + hd;
            store_split_pair(base, w0, w1, which == 0);  // q: pattern A, k: pattern B
        }
    } else {  // mode 1: pk (B-pat), pq (A-pat)
        unsigned short* base = ((which == 0) ? s0 : s1)
            + (((size_t)h * 768) + mrow) * kKS + hd;
        store_split_pair(base, w0, w1, which == 1);
    }
}

__global__ __launch_bounds__(256) void tgemm_kernel(
    const __nv_bfloat16* __restrict__ A, const __nv_bfloat16* __restrict__ B,
    int K3, int Msrc,
    const float* __restrict__ bias0, const float* __restrict__ bias1,
    const float* __restrict__ bias2,
    float* __restrict__ out0,
    unsigned short* __restrict__ s0, unsigned short* __restrict__ s1,
    int mode)
{
    extern __shared__ __align__(16) char smem[];
    const uint32_t sbase = smem_to_u32(smem);

    const int t = threadIdx.x, lane = t & 31, wid = t >> 5;
    const int warp_m = wid & 1, warp_n = wid >> 1;   // 2 x 4
    const int m0 = blockIdx.y * 128, n0 = blockIdx.x * 128;

    const __nv_bfloat16* Ag = A + (size_t)m0 * K3;
    const __nv_bfloat16* Bg = B + (size_t)n0 * K3;
    const int NC = K3 / BK;

    const int lrow = t >> 3;
    const int lc8  = (t & 7) * 8;

    auto issue = [&](int c) {
        const int buf = c & 1;
        const uint32_t dA = sbase + buf * 2 * TBUF;
        const uint32_t dB = dA + TBUF;
        const __nv_bfloat16* Ak = Ag + (size_t)c * BK;
        const __nv_bfloat16* Bk = Bg + (size_t)c * BK;
#pragma unroll
        for (int it = 0; it < 4; it++) {
            int r = lrow + it * 32;
            uint32_t so = (uint32_t)(r * LDT + lc8) * 2;
            cp_async16(dA + so, Ak + (size_t)r * K3 + lc8);
            cp_async16(dB + so, Bk + (size_t)r * K3 + lc8);
        }
        CP_COMMIT();
    };

    float d[4][4][4];
#pragma unroll
    for (int i = 0; i < 4; i++)
#pragma unroll
        for (int j = 0; j < 4; j++)
#pragma unroll
            for (int e = 0; e < 4; e++) d[i][j][e] = 0.f;

    const int a_row = warp_m * 64 + (lane & 15);
    const int a_col = (lane >> 4) * 8;
    const int b_row = warp_n * 32 + (lane & 7);
    const int b_col = ((lane >> 3) & 1) * 8;

    issue(0);

    for (int c = 0; c < NC; c++) {
        if (c + 1 < NC) { issue(c + 1); CP_WAIT(1); }
        else           { CP_WAIT(0); }
        __syncthreads();

        const int buf = c & 1;
        const uint32_t sA = sbase + buf * 2 * TBUF;
        const uint32_t sB = sA + TBUF;

#pragma unroll
        for (int ks = 0; ks < BK; ks += 16) {
            uint32_t a[4][4], b[4][2];
#pragma unroll
            for (int i = 0; i < 4; i++)
                ldmatrix_x4(a[i], sA + (uint32_t)((a_row + i * 16) * LDT + a_col + ks) * 2);
#pragma unroll
            for (int j = 0; j < 4; j++)
                ldmatrix_x2(b[j], sB + (uint32_t)((b_row + j * 8) * LDT + b_col + ks) * 2);
#pragma unroll
            for (int i = 0; i < 4; i++)
#pragma unroll
                for (int j = 0; j < 4; j++)
                    mma_bf16(d[i][j], a[i], b[j]);
        }
        __syncthreads();
    }

    const int mbase = m0 + warp_m * 64 + (lane >> 2);
    const int nbase = n0 + warp_n * 32 + (lane & 3) * 2;
#pragma unroll
    for (int i = 0; i < 4; i++) {
#pragma unroll
        for (int j = 0; j < 4; j++) {
            int mm = mbase + i * 16;
            int nn = nbase + j * 8;
            store_pair(mode, Msrc, mm,     nn, d[i][j][0], d[i][j][1],
                       bias0, bias1, bias2, out0, s0, s1);
            store_pair(mode, Msrc, mm + 8, nn, d[i][j][2], d[i][j][3],
                       bias0, bias1, bias2, out0, s0, s1);
        }
    }
}

// ---------------------------------------------------------------------------
// Fused banded-MMA logits kernel.
// Per block: (bh, 64 i-rows, 64 j-cols). Three HMMA products over K=192 split:
//   c2c[i,j] = q_i . k_j
//   QW[i,u]  = q_i . pk[rb+u]   (window, u in [0,128))
//   KW[j,u]  = k_j . pq[rb+u]
// with rb = i0 - j0 + 320;  then logits = (c2c + QW[i,i-j+63] + KW[j,i-j+63])
//   * inv + segment bias, masked.
// ---------------------------------------------------------------------------
constexpr int LDS = 200;  // smem stride in halves for all operand tiles
constexpr int LOGMMA_SMEM = (2 * 64 * LDS + 2 * 128 * LDS) * 2;  // 153600 B
constexpr int QW_STRIDE = 132;

__global__ __launch_bounds__(256) void logits_mma_kernel(
    const unsigned short* __restrict__ qs, const unsigned short* __restrict__ ks,
    const unsigned short* __restrict__ pks, const unsigned short* __restrict__ pqs,
    const int* __restrict__ mask, const int* __restrict__ seg,
    const float* __restrict__ sep,
    const float* __restrict__ same_bias, const float* __restrict__ cross_bias,
    const float* __restrict__ sep_scale, const float* __restrict__ sep_decay,
    float* __restrict__ logits)
{
    extern __shared__ __align__(16) char smem[];
    const uint32_t sb = smem_to_u32(smem);

    __shared__ int   s_segi[64], s_segj[64], s_maskj[64];
    __shared__ float s_sepi[64], s_sepj[64];

    const int t = threadIdx.x, lane = t & 31, wid = t >> 5;
    const int wm = wid >> 2, wn = wid & 3;          // 2 x 4 warps
    const int bh = blockIdx.z, b = bh / kH, h = bh % kH;
    const int i0 = blockIdx.y * 64, j0 = blockIdx.x * 64;
    const int rb = i0 - j0 + 320;                   // window base: r = rb + u

    // smem layout (halves): Q[64][200], K[64][200], PK[128][200], PQ[128][200]
    const uint32_t sQ  = sb;
    const uint32_t sK  = sQ + 64 * LDS * 2;
    const uint32_t sPK = sK + 64 * LDS * 2;
    const uint32_t sPQ = sPK + 128 * LDS * 2;

    // metadata
    if (t < 64) {
        s_segi[t] = seg[b * kS + i0 + t];
        s_sepi[t] = fabsf(sep[b * kS + i0 + t]);
    } else if (t < 128) {
        int u = t - 64;
        s_segj[u]  = seg[b * kS + j0 + u];
        s_sepj[u]  = fabsf(sep[b * kS + j0 + u]);
        s_maskj[u] = mask[b * kS + j0 + u];
    }

    // stage operands via cp.async (one shot, K=192 fits)
    {
        const unsigned short* gq  = qs  + ((size_t)bh * kS + i0) * kKS;
        const unsigned short* gk  = ks  + ((size_t)bh * kS + j0) * kKS;
        const unsigned short* gpk = pks + ((size_t)h * 768 + rb) * kKS;
        const unsigned short* gpq = pqs + ((size_t)h * 768 + rb) * kKS;
        const int r0 = t >> 3;           // 0..31
        const int c0 = (t & 7);          // chunk base (of 24 16B-chunks per row)
#pragma unroll
        for (int rh = 0; rh < 2; rh++) {
#pragma unroll
            for (int cc = 0; cc < 3; cc++) {
                int row = r0 + rh * 32, ch = c0 + cc * 8;
                uint32_t so = (uint32_t)(row * LDS + ch * 8) * 2;
                cp_async16(sQ + so, gq + (size_t)row * kKS + ch * 8);
                cp_async16(sK + so, gk + (size_t)row * kKS + ch * 8);
            }
        }
#pragma unroll
        for (int rh = 0; rh < 4; rh++) {
#pragma unroll
            for (int cc = 0; cc < 3; cc++) {
                int row = r0 + rh * 32, ch = c0 + cc * 8;
                uint32_t so = (uint32_t)(row * LDS + ch * 8) * 2;
                cp_async16(sPK + so, gpk + (size_t)row * kKS + ch * 8);
                cp_async16(sPQ + so, gpq + (size_t)row * kKS + ch * 8);
            }
        }
        CP_COMMIT();
        CP_WAIT(0);
    }
    __syncthreads();

    // MMA phase
    float c2c[2][2][4], qw[2][4][4], kw[2][4][4];
#pragma unroll
    for (int i = 0; i < 2; i++) {
#pragma unroll
        for (int j = 0; j < 2; j++)
#pragma unroll
            for (int e = 0; e < 4; e++) c2c[i][j][e] = 0.f;
#pragma unroll
        for (int j = 0; j < 4; j++)
#pragma unroll
            for (int e = 0; e < 4; e++) { qw[i][j][e] = 0.f; kw[i][j][e] = 0.f; }
    }

    const int aRow = (lane & 15);
    const int aCol = (lane >> 4) * 8;
    const int bRow = (lane & 7);
    const int bCol = ((lane >> 3) & 1) * 8;

#pragma unroll
    for (int ksp = 0; ksp < kKS; ksp += 16) {
        uint32_t aQ[2][4], aK[2][4];
#pragma unroll
        for (int fi = 0; fi < 2; fi++) {
            int r = wm * 32 + fi * 16 + aRow;
            ldmatrix_x4(aQ[fi], sQ + (uint32_t)(r * LDS + aCol + ksp) * 2);
            ldmatrix_x4(aK[fi], sK + (uint32_t)(r * LDS + aCol + ksp) * 2);
        }
        uint32_t bC[2][2];
#pragma unroll
        for (int fj = 0; fj < 2; fj++) {
            int r = wn * 16 + fj * 8 + bRow;
            ldmatrix_x2(bC[fj], sK + (uint32_t)(r * LDS + bCol + ksp) * 2);
        }
        uint32_t bPK[4][2], bPQ[4][2];
#pragma unroll
        for (int fu = 0; fu < 4; fu++) {
            int r = wn * 32 + fu * 8 + bRow;
            ldmatrix_x2(bPK[fu], sPK + (uint32_t)(r * LDS + bCol + ksp) * 2);
            ldmatrix_x2(bPQ[fu], sPQ + (uint32_t)(r * LDS + bCol + ksp) * 2);
        }
#pragma unroll
        for (int fi = 0; fi < 2; fi++)
#pragma unroll
            for (int fj = 0; fj < 2; fj++)
                mma_bf16(c2c[fi][fj], aQ[fi], bC[fj]);
#pragma unroll
        for (int fi = 0; fi < 2; fi++)
#pragma unroll
            for (int fu = 0; fu < 4; fu++) {
                mma_bf16(qw[fi][fu], aQ[fi], bPK[fu]);
                mma_bf16(kw[fi][fu], aK[fi], bPQ[fu]);
            }
    }

    // stage QW/KW to smem (reuse operand smem; all reads done)
    __syncthreads();
    float* QWs = (float*)smem;                    // [64][132]
    float* KWs = QWs + 64 * QW_STRIDE;            // [64][132]
#pragma unroll
    for (int fi = 0; fi < 2; fi++) {
#pragma unroll
        for (int fu = 0; fu < 4; fu++) {
            int rl = wm * 32 + fi * 16 + (lane >> 2);
            int u  = wn * 32 + fu * 8 + (lane & 3) * 2;
            QWs[rl * QW_STRIDE + u]           = qw[fi][fu][0];
            QWs[rl * QW_STRIDE + u + 1]       = qw[fi][fu][1];
            QWs[(rl + 8) * QW_STRIDE + u]     = qw[fi][fu][2];
            QWs[(rl + 8) * QW_STRIDE + u + 1] = qw[fi][fu][3];
            KWs[rl * QW_STRIDE + u]           = kw[fi][fu][0];
            KWs[rl * QW_STRIDE + u + 1]       = kw[fi][fu][1];
            KWs[(rl + 8) * QW_STRIDE + u]     = kw[fi][fu][2];
            KWs[(rl + 8) * QW_STRIDE + u + 1] = kw[fi][fu][3];
        }
    }
    __syncthreads();

    // combine + bias + mask + store
    const float sb_same  = same_bias[h];
    const float sb_cross = cross_bias[h];
    const float scale_h  = sep_scale[h];
    const float dx       = sep_decay[h];
    const float softp    = fmaxf(dx, 0.f) + log1pf(expf(-fabsf(dx)));
    const float decay    = softp + 1e-4f;
    const float inv      = 0.07216878364870322f;  // 1/sqrt(3*HD)

#pragma unroll
    for (int fi = 0; fi < 2; fi++) {
#pragma unroll
        for (int fj = 0; fj < 2; fj++) {
            int il0 = wm * 32 + fi * 16 + (lane >> 2);
            int jl0 = wn * 16 + fj * 8 + (lane & 3) * 2;
#pragma unroll
            for (int half = 0; half < 2; half++) {
                int il = il0 + half * 8;
                float raw0 = c2c[fi][fj][half * 2];
                float raw1 = c2c[fi][fj][half * 2 + 1];
                int   segi = s_segi[il];
                float sepi = s_sepi[il];
#pragma unroll
                for (int e = 0; e < 2; e++) {
                    int jl = jl0 + e;
                    int u  = il - jl + 63;
                    float val = ((e ? raw1 : raw0)
                                 + QWs[il * QW_STRIDE + u]
                                 + KWs[jl * QW_STRIDE + u]) * inv;
                    if (segi == s_segj[jl]) {
                        val += sb_same;
                    } else {
                        float gap = fabsf(sepi - s_sepj[jl]);
                        val += sb_cross + expf(-gap * decay) * scale_h;
                    }
                    if (s_maskj[jl] == 0) val = -9e15f;
                    logits[(((size_t)bh * kS) + i0 + il) * kS + j0 + jl] = val;
                }
            }
        }
    }
}

// ---------------------------------------------------------------------------
// Row softmax over S=384  (unchanged)
// ---------------------------------------------------------------------------
__global__ __launch_bounds__(128) void softmax_kernel(float* __restrict__ logits)
{
    const size_t row = blockIdx.x;
    float* p = logits + row * kS;
    const int t = threadIdx.x;

    float v0 = p[t], v1 = p[t + 128], v2 = p[t + 256];
    float m = fmaxf(v0, fmaxf(v1, v2));

    __shared__ float red[4];
#pragma unroll
    for (int o = 16; o; o >>= 1) m = fmaxf(m, __shfl_xor_sync(0xffffffffu, m, o));
    if ((t & 31) == 0) red[t >> 5] = m;
    __syncthreads();
    m = fmaxf(fmaxf(red[0], red[1]), fmaxf(red[2], red[3]));

    float e0 = expf(v0 - m), e1 = expf(v1 - m), e2 = expf(v2 - m);
    float s = e0 + e1 + e2;
#pragma unroll
    for (int o = 16; o; o >>= 1) s += __shfl_xor_sync(0xffffffffu, s, o);
    __shared__ float red2[4];
    if ((t & 31) == 0) red2[t >> 5] = s;
    __syncthreads();
    s = red2[0] + red2[1] + red2[2] + red2[3];

    float r = 1.f / s;
    p[t] = e0 * r; p[t + 128] = e1 * r; p[t + 256] = e2 * r;
}

// ---------------------------------------------------------------------------
// AV: vals[b,i,h*HD+d] = sum_j attn[b,h,i,j] * v[b,h,j,d]  (unchanged)
// ---------------------------------------------------------------------------
__global__ __launch_bounds__(256) void av_kernel(
    const float* __restrict__ attn, const float* __restrict__ v,
    float* __restrict__ vals)
{
    __shared__ __align__(16) float As[32][68];
    __shared__ __align__(16) float Vs[32][68];

    const int bh = blockIdx.y, b = bh / kH, h = bh % kH;
    const int i0 = blockIdx.x * 64;
    const float* A = attn + (size_t)bh * kS * kS;
    const float* V = v + (size_t)bh * kS * kHD;

    const int t  = threadIdx.x;
    const int tx = t & 15, ty = t >> 4;

    float acc[4][4] = {};

    for (int k0 = 0; k0 < kS; k0 += 32) {
        float4 ar[2], vr[2];
#pragma unroll
        for (int l = 0; l < 2; l++) {
            int lin = t + 256 * l;
            int arow = lin >> 3, ac4 = (lin & 7) << 2;
            ar[l] = *(const float4*)&A[(size_t)(i0 + arow) * kS + k0 + ac4];
            int vrow = lin >> 4, vc4 = (lin & 15) << 2;
            vr[l] = *(const float4*)&V[(size_t)(k0 + vrow) * kHD + vc4];
        }
        __syncthreads();
#pragma unroll
        for (int l = 0; l < 2; l++) {
            int lin = t + 256 * l;
            int arow = lin >> 3, ac4 = (lin & 7) << 2;
            As[ac4 + 0][arow] = ar[l].x; As[ac4 + 1][arow] = ar[l].y;
            As[ac4 + 2][arow] = ar[l].z; As[ac4 + 3][arow] = ar[l].w;
            int vrow = lin >> 4, vc4 = (lin & 15) << 2;
            *(float4*)&Vs[vrow][vc4] = vr[l];
        }
        __syncthreads();
#pragma unroll
        for (int kk = 0; kk < 32; kk++) {
            float4 a4 = *(const float4*)&As[kk][ty << 2];
            float4 b4 = *(const float4*)&Vs[kk][tx << 2];
            float a[4] = {a4.x, a4.y, a4.z, a4.w};
            float bb[4] = {b4.x, b4.y, b4.z, b4.w};
#pragma unroll
            for (int ii = 0; ii < 4; ii++)
#pragma unroll
                for (int jj = 0; jj < 4; jj++)
                    acc[ii][jj] += a[ii] * bb[jj];
        }
    }

#pragma unroll
    for (int ii = 0; ii < 4; ii++) {
        int i = i0 + (ty << 2) + ii;
#pragma unroll
        for (int jj = 0; jj < 4; jj++) {
            int dd = (tx << 2) + jj;
            vals[((size_t)b * kS + i) * kE + h * kHD + dd] = acc[ii][jj];
        }
    }
}

// ---------------------------------------------------------------------------
// Launch
// ---------------------------------------------------------------------------
extern "C" void kernel_launch(void* const* d_in, const int* in_sizes, int n_in,
                              void* d_out, int out_size)
{
    const float* x    = (const float*)d_in[0];
    const int*   mask = (const int*)d_in[1];
    const int*   seg  = (const int*)d_in[2];
    const float* sep  = (const float*)d_in[3];
    const float* Wq   = (const float*)d_in[4];
    const float* bq   = (const float*)d_in[5];
    const float* Wk   = (const float*)d_in[6];
    const float* bk   = (const float*)d_in[7];
    const float* Wv   = (const float*)d_in[8];
    const float* bv   = (const float*)d_in[9];
    const float* rel  = (const float*)d_in[10];
    const float* Wpk  = (const float*)d_in[11];
    const float* bpk  = (const float*)d_in[12];
    const float* Wpq  = (const float*)d_in[13];
    const float* bpq  = (const float*)d_in[14];
    const float* same_b  = (const float*)d_in[15];
    const float* cross_b = (const float*)d_in[16];
    const float* sscale  = (const float*)d_in[17];
    const float* sdecay  = (const float*)d_in[18];
    const float* Wo   = (const float*)d_in[19];
    const float* bo   = (const float*)d_in[20];
    float* out = (float*)d_out;

    float *v_, *lg_, *vl_;
    unsigned short *ab_, *wqkv_, *apos_, *wpos_, *qs_, *ks_, *pks_, *pqs_;
    cudaGetSymbolAddress((void**)&v_,  g_v);
    cudaGetSymbolAddress((void**)&lg_, g_logits);
    cudaGetSymbolAddress((void**)&vl_, g_vals);
    cudaGetSymbolAddress((void**)&ab_,   g_ab);
    cudaGetSymbolAddress((void**)&wqkv_, g_wqkv);
    cudaGetSymbolAddress((void**)&apos_, g_apos);
    cudaGetSymbolAddress((void**)&wpos_, g_wpos);
    cudaGetSymbolAddress((void**)&qs_,  g_qs);
    cudaGetSymbolAddress((void**)&ks_,  g_ks);
    cudaGetSymbolAddress((void**)&pks_, g_pks);
    cudaGetSymbolAddress((void**)&pqs_, g_pqs);

    cudaFuncSetAttribute(tgemm_kernel,
                         cudaFuncAttributeMaxDynamicSharedMemorySize,
                         TGEMM_SMEM);
    cudaFuncSetAttribute(logits_mma_kernel,
                         cudaFuncAttributeMaxDynamicSharedMemorySize,
                         LOGMMA_SMEM);

    const int kq = kD / 4;  // 192

    // 1) operand splits (fp32 -> bf16 hi/lo, K-concat)
    split_a_kernel<<<(3072 * kq + 255) / 256, 256>>>(x, ab_, 3072, 3072, kD);
    split_w_kernel<<<(2304 * kq + 255) / 256, 256>>>(Wq, Wk, Wv, wqkv_, 3, kD);
    split_a_kernel<<<(768 * kq + 255) / 256, 256>>>(rel + (size_t)128 * kD, apos_, kR, 768, kD);
    split_w_kernel<<<(1536 * kq + 255) / 256, 256>>>(Wpk, Wpq, Wpq, wpos_, 2, kD);

    // 2) QKV projection (merged): q,k -> bf16 split; v -> fp32
    tgemm_kernel<<<dim3(18, 24), 256, TGEMM_SMEM>>>(
        (const __nv_bfloat16*)ab_, (const __nv_bfloat16*)wqkv_, kK3, 3072,
        bq, bk, bv, v_, qs_, ks_, 0);

    // 3) positional projections (merged): pk,pq -> bf16 split
    tgemm_kernel<<<dim3(12, 6), 256, TGEMM_SMEM>>>(
        (const __nv_bfloat16*)apos_, (const __nv_bfloat16*)wpos_, kK3, kR,
        bpk, bpq, nullptr, nullptr, pks_, pqs_, 1);

    // 4) fused banded-MMA logits + segment bias + mask
    dim3 glog(kS / 64, kS / 64, kB * kH);
    logits_mma_kernel<<<glog, 256, LOGMMA_SMEM>>>(
        qs_, ks_, pks_, pqs_, mask, seg, sep,
        same_b, cross_b, sscale, sdecay, lg_);

    // 5) Softmax over keys
    softmax_kernel<<<kB * kH * kS, 128>>>(lg_);

    // 6) attn @ V -> vals [B,S,E]
    dim3 gav(kS / 64, kB * kH);
    av_kernel<<<gav, 256>>>(lg_, v_, vl_);

    // 7) Output projection
    split_a_kernel<<<(3072 * kq + 255) / 256, 256>>>(vl_, ab_, 3072, 3072, kE);
    split_w_kernel<<<(768 * kq + 255) / 256, 256>>>(Wo, Wo, Wo, wpos_, 1, kE);
    tgemm_kernel<<<dim3(6, 24), 256, TGEMM_SMEM>>>(
        (const __nv_bfloat16*)ab_, (const __nv_bfloat16*)wpos_, kK3, 3072,
        bo, nullptr, nullptr, out, nullptr, nullptr, 2);
}